// round 7
// baseline (speedup 1.0000x reference)
#include <cuda_runtime.h>
#include <cstdint>

#define B_   8
#define CIN  64
#define COUT 128
#define L_   18
#define LV   16
#define H_   32
#define W_   32
#define HW   1024
#define NH   2
#define DQ   9
#define DV   8

// Scratch (static device globals; no runtime allocation allowed)
__device__ float g_q[B_*COUT*L_*HW];          // 75.5 MB
__device__ float g_k[B_*COUT*L_*HW];          // 75.5 MB
__device__ float g_v[B_*COUT*LV*HW];          // 67 MB
__device__ float g_lp[B_*NH*DQ*COUT*COUT];    // 9.4 MB (per-depth logit partials)
__device__ float g_attn[B_*NH*COUT*COUT];     // 1 MB

typedef unsigned long long ull;

// ---------------------------------------------------------------------------
// tf32 helpers
// ---------------------------------------------------------------------------
__device__ __forceinline__ float tf32_round(float x) {
    uint32_t u;
    asm("cvt.rna.tf32.f32 %0, %1;" : "=r"(u) : "f"(x));
    return __uint_as_float(u);
}
__device__ __forceinline__ float xform(float x, bool lo) {
    float h = tf32_round(x);
    return lo ? (x - h) : h;
}

// mma.sync m16n8k8 tf32 (legacy tensor path — baseline PTX, works on sm_103)
__device__ __forceinline__ void mma_tf32(float* d, const uint32_t* a,
                                         uint32_t b0, uint32_t b1) {
    asm volatile(
        "mma.sync.aligned.m16n8k8.row.col.f32.tf32.tf32.f32 "
        "{%0,%1,%2,%3}, {%4,%5,%6,%7}, {%8,%9}, {%0,%1,%2,%3};"
        : "+f"(d[0]), "+f"(d[1]), "+f"(d[2]), "+f"(d[3])
        : "r"(a[0]), "r"(a[1]), "r"(a[2]), "r"(a[3]), "r"(b0), "r"(b1));
}

// f32x2 helpers (out_kernel)
__device__ __forceinline__ ull pack2(float x, float y) {
    ull r; asm("mov.b64 %0, {%1, %2};" : "=l"(r) : "f"(x), "f"(y)); return r;
}
__device__ __forceinline__ float2 unpack2(ull v) {
    float2 r; asm("mov.b64 {%0, %1}, %2;" : "=f"(r.x), "=f"(r.y) : "l"(v)); return r;
}
__device__ __forceinline__ void ffma2(ull& d, ull a, ull b) {
    asm("fma.rn.f32x2 %0, %1, %2, %0;" : "+l"(d) : "l"(a), "l"(b));
}

#define KC     32          // K chunk per smem stage
#define SSTR   36          // smem row stride (floats): conflict-free frag reads

// ---------------------------------------------------------------------------
// Implicit-GEMM conv via mma.sync tf32x3.
// D[co=128, hw=128] = W[co, K3] * P[hw, K3], K3 = 3*CIN*TAPS (hi/lo segments)
// grid (8 hw-tiles, LOUT, B_), block 256 (8 warps, each 32co x 64hw).
// ---------------------------------------------------------------------------
template<int TAPS, int LOUT>
__global__ __launch_bounds__(256, 2) void conv_mma_kernel(
    const float* __restrict__ in, const float* __restrict__ wgt,
    const float* __restrict__ bias, float* __restrict__ dst, float scale)
{
    constexpr int KSEG = CIN * TAPS;          // 576 or 1728
    constexpr int NCHUNK = 3 * KSEG / KC;     // 54 or 162
    __shared__ float As[128 * SSTR];          // [co][k]
    __shared__ float Bs[128 * SSTR];          // [hw][k]

    const int tid = threadIdx.x;
    const int wid = tid >> 5;
    const int lid = tid & 31;
    const int wm  = wid & 3;                  // m warp: co rows 32*wm
    const int wn  = wid >> 2;                 // n warp: hw cols 64*wn
    const int nt_ = blockIdx.x;
    const int l   = blockIdx.y;
    const int b   = blockIdx.z;
    const int hw0 = nt_ << 7;

    const float* inb = in + (size_t)b*CIN*L_*HW + (size_t)l*HW;

    float acc[2][8][4];
#pragma unroll
    for (int i = 0; i < 2; i++)
#pragma unroll
        for (int j = 0; j < 8; j++)
#pragma unroll
            for (int r = 0; r < 4; r++) acc[i][j][r] = 0.f;

#pragma unroll 1
    for (int c = 0; c < NCHUNK; c++) {
        const int seg = (c * KC) / KSEG;
        const int tb  = c * KC - seg * KSEG;

        // A tile: 128 co x 32 k (weights; seg2 -> residual)
        {
            const bool lo = (seg == 2);
#pragma unroll
            for (int q = 0; q < 4; q++) {
                int idx = tid + q * 256;           // 0..1023 float4 slots
                int row = idx >> 3;
                int col = (idx & 7) << 2;
                float4 v = *(const float4*)(wgt + (size_t)row * KSEG + tb + col);
                v.x = xform(v.x, lo); v.y = xform(v.y, lo);
                v.z = xform(v.z, lo); v.w = xform(v.w, lo);
                *(float4*)&As[row * SSTR + col] = v;
            }
        }
        // B tile: 128 hw x 32 k (im2col; seg1 -> residual)
        {
            const bool lo = (seg == 1);
#pragma unroll
            for (int q = 0; q < 16; q++) {
                int idx = tid + q * 256;           // 0..4095
                int n   = idx & 127;
                int tq  = idx >> 7;                // 0..31
                int p   = hw0 + n;
                int h   = p >> 5;
                int w   = p & 31;
                int t   = tb + tq;
                int ci  = t / TAPS;
                int tap = t - ci * TAPS;
                int dl, dh, dw;
                if (TAPS == 27) { dl = tap / 9; int r = tap - dl * 9; dh = r / 3; dw = r - dh * 3; }
                else            { dl = 0; dh = tap / 3; dw = tap - dh * 3; }
                int hh = h + dh - 1, ww = w + dw - 1;
                float x = 0.f;
                if ((unsigned)hh < (unsigned)H_ && (unsigned)ww < (unsigned)W_)
                    x = inb[((size_t)ci * L_ + dl) * HW + hh * W_ + ww];
                Bs[n * SSTR + tq] = xform(x, lo);
            }
        }
        __syncthreads();

#pragma unroll
        for (int ks = 0; ks < 4; ks++) {
            const int kb = ks << 3;
            uint32_t a[2][4];
#pragma unroll
            for (int mt = 0; mt < 2; mt++) {
                int row = (wm << 5) + (mt << 4) + (lid >> 2);
                int col = kb + (lid & 3);
                a[mt][0] = __float_as_uint(As[row * SSTR + col]);
                a[mt][1] = __float_as_uint(As[(row + 8) * SSTR + col]);
                a[mt][2] = __float_as_uint(As[row * SSTR + col + 4]);
                a[mt][3] = __float_as_uint(As[(row + 8) * SSTR + col + 4]);
            }
#pragma unroll
            for (int nt = 0; nt < 8; nt++) {
                int n  = (wn << 6) + (nt << 3) + (lid >> 2);
                uint32_t b0 = __float_as_uint(Bs[n * SSTR + kb + (lid & 3)]);
                uint32_t b1 = __float_as_uint(Bs[n * SSTR + kb + 4 + (lid & 3)]);
                mma_tf32(acc[0][nt], a[0], b0, b1);
                mma_tf32(acc[1][nt], a[1], b0, b1);
            }
        }
        __syncthreads();
    }

    // Epilogue: c0,c1 -> (row, col{+0,+1}); c2,c3 -> (row+8, col{+0,+1})
#pragma unroll
    for (int mt = 0; mt < 2; mt++) {
        int co = (wm << 5) + (mt << 4) + (lid >> 2);
        float bi0 = bias[co];
        float bi1 = bias[co + 8];
        float* d0 = dst + (((size_t)b * COUT + co)     * LOUT + l) * HW + hw0;
        float* d1 = dst + (((size_t)b * COUT + co + 8) * LOUT + l) * HW + hw0;
#pragma unroll
        for (int nt = 0; nt < 8; nt++) {
            int colp = (wn << 6) + (nt << 3) + ((lid & 3) << 1);
            float2 v0 = make_float2((acc[mt][nt][0] + bi0) * scale,
                                    (acc[mt][nt][1] + bi0) * scale);
            float2 v1 = make_float2((acc[mt][nt][2] + bi1) * scale,
                                    (acc[mt][nt][3] + bi1) * scale);
            *(float2*)(d0 + colp) = v0;
            *(float2*)(d1 + colp) = v1;
        }
    }
}

// ---------------------------------------------------------------------------
// Logit per (b,n,d): D[c=128, m=128] = sum_hw q*k, tf32x3 (K3 = 3*1024)
// grid 144, block 256.
// ---------------------------------------------------------------------------
__global__ __launch_bounds__(256, 2) void logit_mma_kernel(
    const float* __restrict__ q, const float* __restrict__ k, float* __restrict__ lp)
{
    constexpr int KSEG = HW;                  // 1024
    constexpr int NCHUNK = 3 * KSEG / KC;     // 96
    __shared__ float As[128 * SSTR];
    __shared__ float Bs[128 * SSTR];

    const int tid = threadIdx.x;
    const int wid = tid >> 5;
    const int lid = tid & 31;
    const int wm  = wid & 3;
    const int wn  = wid >> 2;
    const int bnd = blockIdx.x;               // bn*DQ + d
    const int d   = bnd % DQ;
    const int bn  = bnd / DQ;
    const int n_  = bn & 1;
    const int b   = bn >> 1;
    const int ldep = n_ * DQ + d;

    const float* qb = q + ((size_t)b * COUT * L_ + ldep) * HW;
    const float* kb = k + ((size_t)b * COUT * L_ + ldep) * HW;

    float acc[2][8][4];
#pragma unroll
    for (int i = 0; i < 2; i++)
#pragma unroll
        for (int j = 0; j < 8; j++)
#pragma unroll
            for (int r = 0; r < 4; r++) acc[i][j][r] = 0.f;

#pragma unroll 1
    for (int c = 0; c < NCHUNK; c++) {
        const int seg = (c * KC) / KSEG;
        const int tb  = c * KC - seg * KSEG;
        const bool loA = (seg == 1);
        const bool loB = (seg == 2);
#pragma unroll
        for (int qq = 0; qq < 4; qq++) {
            int idx = tid + qq * 256;
            int row = idx >> 3;
            int col = (idx & 7) << 2;
            float4 va = *(const float4*)(qb + (size_t)row * (L_*HW) + tb + col);
            va.x = xform(va.x, loA); va.y = xform(va.y, loA);
            va.z = xform(va.z, loA); va.w = xform(va.w, loA);
            *(float4*)&As[row * SSTR + col] = va;
            float4 vb = *(const float4*)(kb + (size_t)row * (L_*HW) + tb + col);
            vb.x = xform(vb.x, loB); vb.y = xform(vb.y, loB);
            vb.z = xform(vb.z, loB); vb.w = xform(vb.w, loB);
            *(float4*)&Bs[row * SSTR + col] = vb;
        }
        __syncthreads();

#pragma unroll
        for (int ks = 0; ks < 4; ks++) {
            const int kb2 = ks << 3;
            uint32_t a[2][4];
#pragma unroll
            for (int mt = 0; mt < 2; mt++) {
                int row = (wm << 5) + (mt << 4) + (lid >> 2);
                int col = kb2 + (lid & 3);
                a[mt][0] = __float_as_uint(As[row * SSTR + col]);
                a[mt][1] = __float_as_uint(As[(row + 8) * SSTR + col]);
                a[mt][2] = __float_as_uint(As[row * SSTR + col + 4]);
                a[mt][3] = __float_as_uint(As[(row + 8) * SSTR + col + 4]);
            }
#pragma unroll
            for (int nt = 0; nt < 8; nt++) {
                int n  = (wn << 6) + (nt << 3) + (lid >> 2);
                uint32_t b0 = __float_as_uint(Bs[n * SSTR + kb2 + (lid & 3)]);
                uint32_t b1 = __float_as_uint(Bs[n * SSTR + kb2 + 4 + (lid & 3)]);
                mma_tf32(acc[0][nt], a[0], b0, b1);
                mma_tf32(acc[1][nt], a[1], b0, b1);
            }
        }
        __syncthreads();
    }

    float* o = lp + (size_t)bnd * COUT * COUT;
#pragma unroll
    for (int mt = 0; mt < 2; mt++) {
        int cc = (wm << 5) + (mt << 4) + (lid >> 2);
#pragma unroll
        for (int nt = 0; nt < 8; nt++) {
            int m = (wn << 6) + (nt << 3) + ((lid & 3) << 1);
            *(float2*)(o + (size_t)cc * COUT + m) =
                make_float2(acc[mt][nt][0], acc[mt][nt][1]);
            *(float2*)(o + (size_t)(cc + 8) * COUT + m) =
                make_float2(acc[mt][nt][2], acc[mt][nt][3]);
        }
    }
}

// ---------------------------------------------------------------------------
// Sum DQ partials + row softmax over m. One block per (bn, c).
// ---------------------------------------------------------------------------
__global__ __launch_bounds__(128) void softmax_kernel(
    const float* __restrict__ lp, float* __restrict__ attn)
{
    const int row = blockIdx.x;
    const int bn  = row >> 7;
    const int c   = row & 127;
    const int m   = threadIdx.x;

    float s = 0.f;
#pragma unroll
    for (int dd = 0; dd < DQ; dd++)
        s += lp[(((size_t)(bn*DQ + dd))*COUT + c)*COUT + m];

    __shared__ float red[128];
    red[m] = s;
    __syncthreads();
    for (int off = 64; off > 0; off >>= 1) {
        if (m < off) red[m] = fmaxf(red[m], red[m + off]);
        __syncthreads();
    }
    float mx = red[0];
    __syncthreads();
    float e = expf(s - mx);
    red[m] = e;
    __syncthreads();
    for (int off = 64; off > 0; off >>= 1) {
        if (m < off) red[m] = red[m] + red[m + off];
        __syncthreads();
    }
    attn[row*COUT + m] = e / red[0];
}

// ---------------------------------------------------------------------------
// out[b,c,n*8+d,hw] = sum_m attn[bn,c,m] * v[b,m,n*8+d,hw]  (f32x2 scalar)
// ---------------------------------------------------------------------------
__global__ __launch_bounds__(256) void out_kernel(
    const float* __restrict__ attn, const float* __restrict__ v, float* __restrict__ out)
{
    const int tile = blockIdx.x;
    const int bn   = blockIdx.y;
    const int b    = bn >> 1;
    const int n    = bn & 1;
    const int d    = (tile << 6) >> 10;
    const int hw0  = (tile << 6) & 1023;
    const int tid  = threadIdx.x;
    const int px   = tid & 63;
    const int cg   = tid >> 6;
    const int c0   = cg << 5;
    const int hw   = hw0 + px;

    __shared__ float As2[64*132];
    const float* ab = attn + bn*COUT*COUT;
    const float* vb = v + ((size_t)b*COUT*LV + n*DV + d)*HW + hw;

    ull acc2[16];
#pragma unroll
    for (int j = 0; j < 16; j++) acc2[j] = 0ull;

    for (int mc = 0; mc < 2; mc++) {
        __syncthreads();
        for (int i = tid; i < 64*128; i += 256) {
            int ml = i & 63;
            int c  = i >> 6;
            As2[ml*132 + c] = ab[c*COUT + (mc << 6) + ml];
        }
        __syncthreads();
#pragma unroll 4
        for (int ml = 0; ml < 64; ml++) {
            float vv = vb[((size_t)((mc << 6) + ml))*(LV*HW)];
            ull vp = pack2(vv, vv);
            const ull* ap = (const ull*)&As2[ml*132 + c0];
#pragma unroll
            for (int jj = 0; jj < 16; jj++)
                ffma2(acc2[jj], ap[jj], vp);
        }
    }
    float* ob = out + (((size_t)b*COUT + c0)*(NH*DV) + n*DV + d)*HW + hw;
#pragma unroll
    for (int jj = 0; jj < 16; jj++) {
        float2 a = unpack2(acc2[jj]);
        ob[(size_t)(2*jj)    *(NH*DV*HW)] = a.x;
        ob[(size_t)(2*jj + 1)*(NH*DV*HW)] = a.y;
    }
}

// ---------------------------------------------------------------------------
extern "C" void kernel_launch(void* const* d_in, const int* in_sizes, int n_in,
                              void* d_out, int out_size)
{
    const float* input  = (const float*)d_in[0];
    const float* memory = (const float*)d_in[1];
    const float* wq = (const float*)d_in[2];
    const float* bq = (const float*)d_in[3];
    const float* wk = (const float*)d_in[4];
    const float* bk = (const float*)d_in[5];
    const float* wv = (const float*)d_in[6];
    const float* bv = (const float*)d_in[7];
    float* out = (float*)d_out;

    float *pq, *pk, *pv, *plp, *pattn;
    cudaGetSymbolAddress((void**)&pq,    g_q);
    cudaGetSymbolAddress((void**)&pk,    g_k);
    cudaGetSymbolAddress((void**)&pv,    g_v);
    cudaGetSymbolAddress((void**)&plp,   g_lp);
    cudaGetSymbolAddress((void**)&pattn, g_attn);

    conv_mma_kernel<9, L_> <<<dim3(8, L_, B_), 256>>>(input,  wq, bq, pq, 0.5f);
    conv_mma_kernel<9, L_> <<<dim3(8, L_, B_), 256>>>(memory, wk, bk, pk, 1.0f);
    conv_mma_kernel<27, LV><<<dim3(8, LV, B_), 256>>>(memory, wv, bv, pv, 1.0f);
    logit_mma_kernel       <<<B_*NH*DQ, 256>>>(pq, pk, plp);
    softmax_kernel         <<<B_*NH*COUT, 128>>>(plp, pattn);
    out_kernel             <<<dim3(128, B_*NH), 256>>>(pattn, pv, out);
}

// round 8
// speedup vs baseline: 2.2357x; 2.2357x over previous
#include <cuda_runtime.h>
#include <cuda_fp16.h>
#include <cstdint>

#define B_   8
#define CIN  64
#define COUT 128
#define L_   18
#define LV   16
#define H_   32
#define W_   32
#define HW   1024
#define NH   2
#define DQ   9
#define DV   8
#define KSPL 2            // logit K split

// Scratch (static device globals; no runtime allocation allowed)
__device__ float g_q[B_*COUT*L_*HW];                // 75.5 MB
__device__ float g_k[B_*COUT*L_*HW];                // 75.5 MB
__device__ float g_v[B_*COUT*LV*HW];                // 67 MB
__device__ float g_lp[KSPL*B_*NH*DQ*COUT*COUT];     // 18.9 MB
__device__ float g_attn[B_*NH*COUT*COUT];           // 1 MB

typedef unsigned long long ull;

// ---------------------------------------------------------------------------
// fp16 split helpers
// ---------------------------------------------------------------------------
__device__ __forceinline__ uint32_t f2h2(float x0, float x1) {
    uint32_t r;
    asm("cvt.rn.f16x2.f32 %0, %1, %2;" : "=r"(r) : "f"(x1), "f"(x0));
    return r;   // lo half = x0, hi half = x1 (memory order)
}
__device__ __forceinline__ float2 h2f2(uint32_t u) {
    __half2 h = *(__half2*)&u;
    return __half22float2(h);
}
__device__ __forceinline__ void split2(float x0, float x1, uint32_t& hi, uint32_t& lo) {
    hi = f2h2(x0, x1);
    float2 hf = h2f2(hi);
    lo = f2h2(x0 - hf.x, x1 - hf.y);
}

// mma.sync m16n8k16 fp16 (baseline PTX, works on plain sm_103)
__device__ __forceinline__ void mma_f16(float* d, const uint32_t* a,
                                        uint32_t b0, uint32_t b1) {
    asm volatile(
        "mma.sync.aligned.m16n8k16.row.col.f32.f16.f16.f32 "
        "{%0,%1,%2,%3}, {%4,%5,%6,%7}, {%8,%9}, {%0,%1,%2,%3};"
        : "+f"(d[0]), "+f"(d[1]), "+f"(d[2]), "+f"(d[3])
        : "r"(a[0]), "r"(a[1]), "r"(a[2]), "r"(a[3]), "r"(b0), "r"(b1));
}

// f32x2 helpers (out_kernel)
__device__ __forceinline__ ull pack2(float x, float y) {
    ull r; asm("mov.b64 %0, {%1, %2};" : "=l"(r) : "f"(x), "f"(y)); return r;
}
__device__ __forceinline__ float2 unpack2(ull v) {
    float2 r; asm("mov.b64 {%0, %1}, %2;" : "=f"(r.x), "=f"(r.y) : "l"(v)); return r;
}
__device__ __forceinline__ void ffma2(ull& d, ull a, ull b) {
    asm("fma.rn.f32x2 %0, %1, %2, %0;" : "+l"(d) : "l"(a), "l"(b));
}

#define KC  32          // K elems per chunk
#define SW  20          // smem row stride in 32-bit words (16 data + 4 pad)

// ---------------------------------------------------------------------------
// Fragment-load + 3-segment MMA core shared by conv and logit kernels.
// acc += Ah*Bh + Al*Bh + Ah*Bl over the 32-k chunk in smem.
// ---------------------------------------------------------------------------
__device__ __forceinline__ void mma_chunk(
    float acc[2][8][4],
    const uint32_t* Ah, const uint32_t* Al,
    const uint32_t* Bh, const uint32_t* Bl,
    int wm, int wn, int lid)
{
    const int qr = lid >> 2;
    const int qc = lid & 3;
#pragma unroll
    for (int ks = 0; ks < 2; ks++) {
        const int base = ks << 3;
        uint32_t ah[2][4], al[2][4];
#pragma unroll
        for (int mt = 0; mt < 2; mt++) {
            int r0 = (wm << 5) + (mt << 4) + qr;
            int w0 = r0 * SW + base + qc;
            int w1 = (r0 + 8) * SW + base + qc;
            ah[mt][0] = Ah[w0];     ah[mt][1] = Ah[w1];
            ah[mt][2] = Ah[w0 + 4]; ah[mt][3] = Ah[w1 + 4];
            al[mt][0] = Al[w0];     al[mt][1] = Al[w1];
            al[mt][2] = Al[w0 + 4]; al[mt][3] = Al[w1 + 4];
        }
        uint32_t bf[8][2];
#pragma unroll
        for (int nt = 0; nt < 8; nt++) {
            int n = (wn << 6) + (nt << 3) + qr;
            int w = n * SW + base + qc;
            bf[nt][0] = Bh[w]; bf[nt][1] = Bh[w + 4];
        }
#pragma unroll
        for (int nt = 0; nt < 8; nt++) {
            mma_f16(acc[0][nt], ah[0], bf[nt][0], bf[nt][1]);
            mma_f16(acc[1][nt], ah[1], bf[nt][0], bf[nt][1]);
        }
#pragma unroll
        for (int nt = 0; nt < 8; nt++) {
            mma_f16(acc[0][nt], al[0], bf[nt][0], bf[nt][1]);
            mma_f16(acc[1][nt], al[1], bf[nt][0], bf[nt][1]);
        }
#pragma unroll
        for (int nt = 0; nt < 8; nt++) {
            int n = (wn << 6) + (nt << 3) + qr;
            int w = n * SW + base + qc;
            bf[nt][0] = Bl[w]; bf[nt][1] = Bl[w + 4];
        }
#pragma unroll
        for (int nt = 0; nt < 8; nt++) {
            mma_f16(acc[0][nt], ah[0], bf[nt][0], bf[nt][1]);
            mma_f16(acc[1][nt], ah[1], bf[nt][0], bf[nt][1]);
        }
    }
}

// ---------------------------------------------------------------------------
// Implicit-GEMM conv via mma.sync fp16x3.
// D[co=128, hw=128] = W[co, K] * P[hw, K], K = CIN*TAPS; hi/lo in one pass.
// grid (8 hw-tiles, LOUT, B_), block 256 (8 warps, each 32co x 64hw).
// ---------------------------------------------------------------------------
template<int TAPS, int LOUT>
__global__ __launch_bounds__(256, 2) void conv_mma_kernel(
    const float* __restrict__ in, const float* __restrict__ wgt,
    const float* __restrict__ bias, float* __restrict__ dst, float scale)
{
    constexpr int KSEG = CIN * TAPS;          // 576 or 1728
    constexpr int NCHUNK = KSEG / KC;         // 18 or 54
    __shared__ uint32_t Ah[128*SW], Al[128*SW], Bh[128*SW], Bl[128*SW];

    const int tid = threadIdx.x;
    const int wid = tid >> 5;
    const int lid = tid & 31;
    const int wm  = wid & 3;
    const int wn  = wid >> 2;
    const int l   = blockIdx.y;
    const int b   = blockIdx.z;
    const int hw0 = blockIdx.x << 7;

    const float* inb = in + (size_t)b*CIN*L_*HW + (size_t)l*HW;

    float acc[2][8][4];
#pragma unroll
    for (int i = 0; i < 2; i++)
#pragma unroll
        for (int j = 0; j < 8; j++)
#pragma unroll
            for (int r = 0; r < 4; r++) acc[i][j][r] = 0.f;

    const int kp_b = tid & 15;       // k-pair index for builds
    const int rw_b = tid >> 4;       // row base

#pragma unroll 1
    for (int c = 0; c < NCHUNK; c++) {
        const int tb = c * KC;
        // A tile: weights 128 co x 32 k, split hi/lo
#pragma unroll
        for (int q = 0; q < 8; q++) {
            int row = rw_b + (q << 4);
            float2 wv = *(const float2*)(wgt + (size_t)row * KSEG + tb + (kp_b << 1));
            uint32_t hi, lo;
            split2(wv.x, wv.y, hi, lo);
            Ah[row*SW + kp_b] = hi;
            Al[row*SW + kp_b] = lo;
        }
        // B tile: im2col 128 hw x 32 k, split hi/lo
#pragma unroll
        for (int q = 0; q < 8; q++) {
            int n = rw_b + (q << 4);
            int p = hw0 + n;
            int h = p >> 5;
            int w = p & 31;
            float x[2];
#pragma unroll
            for (int e = 0; e < 2; e++) {
                int t   = tb + (kp_b << 1) + e;
                int ci  = t / TAPS;
                int tap = t - ci * TAPS;
                int dl, dh, dw;
                if (TAPS == 27) { dl = tap / 9; int r = tap - dl * 9; dh = r / 3; dw = r - dh * 3; }
                else            { dl = 0; dh = tap / 3; dw = tap - dh * 3; }
                int hh = h + dh - 1, ww = w + dw - 1;
                x[e] = 0.f;
                if ((unsigned)hh < (unsigned)H_ && (unsigned)ww < (unsigned)W_)
                    x[e] = inb[((size_t)ci * L_ + dl) * HW + hh * W_ + ww];
            }
            uint32_t hi, lo;
            split2(x[0], x[1], hi, lo);
            Bh[n*SW + kp_b] = hi;
            Bl[n*SW + kp_b] = lo;
        }
        __syncthreads();
        mma_chunk(acc, Ah, Al, Bh, Bl, wm, wn, lid);
        __syncthreads();
    }

    // Epilogue
#pragma unroll
    for (int mt = 0; mt < 2; mt++) {
        int co = (wm << 5) + (mt << 4) + (lid >> 2);
        float bi0 = bias[co];
        float bi1 = bias[co + 8];
        float* d0 = dst + (((size_t)b * COUT + co)     * LOUT + l) * HW + hw0;
        float* d1 = dst + (((size_t)b * COUT + co + 8) * LOUT + l) * HW + hw0;
#pragma unroll
        for (int nt = 0; nt < 8; nt++) {
            int colp = (wn << 6) + (nt << 3) + ((lid & 3) << 1);
            *(float2*)(d0 + colp) = make_float2((acc[mt][nt][0] + bi0) * scale,
                                                (acc[mt][nt][1] + bi0) * scale);
            *(float2*)(d1 + colp) = make_float2((acc[mt][nt][2] + bi1) * scale,
                                                (acc[mt][nt][3] + bi1) * scale);
        }
    }
}

// ---------------------------------------------------------------------------
// Logit partial per (ck, b, n, d): D[c=128, m=128] = sum over 512 pixels.
// grid KSPL*144, block 256.
// ---------------------------------------------------------------------------
__global__ __launch_bounds__(256, 2) void logit_mma_kernel(
    const float* __restrict__ q, const float* __restrict__ k, float* __restrict__ lp)
{
    constexpr int NCHUNK = HW / (KC * KSPL);  // 16
    __shared__ uint32_t Ah[128*SW], Al[128*SW], Bh[128*SW], Bl[128*SW];

    const int tid = threadIdx.x;
    const int wid = tid >> 5;
    const int lid = tid & 31;
    const int wm  = wid & 3;
    const int wn  = wid >> 2;
    const int ck  = blockIdx.x / (B_*NH*DQ);
    const int bnd = blockIdx.x % (B_*NH*DQ);
    const int d   = bnd % DQ;
    const int bn  = bnd / DQ;
    const int n_  = bn & 1;
    const int b   = bn >> 1;
    const int ldep = n_ * DQ + d;

    const float* qb = q + ((size_t)b * COUT * L_ + ldep) * HW;
    const float* kb = k + ((size_t)b * COUT * L_ + ldep) * HW;

    float acc[2][8][4];
#pragma unroll
    for (int i = 0; i < 2; i++)
#pragma unroll
        for (int j = 0; j < 8; j++)
#pragma unroll
            for (int r = 0; r < 4; r++) acc[i][j][r] = 0.f;

    const int kp_b = tid & 15;
    const int rw_b = tid >> 4;

#pragma unroll 1
    for (int c = 0; c < NCHUNK; c++) {
        const int tb = ck * (HW/KSPL) + c * KC;
#pragma unroll
        for (int qq = 0; qq < 8; qq++) {
            int row = rw_b + (qq << 4);
            float2 va = *(const float2*)(qb + (size_t)row * (L_*HW) + tb + (kp_b << 1));
            uint32_t hi, lo;
            split2(va.x, va.y, hi, lo);
            Ah[row*SW + kp_b] = hi;
            Al[row*SW + kp_b] = lo;
            float2 vb = *(const float2*)(kb + (size_t)row * (L_*HW) + tb + (kp_b << 1));
            split2(vb.x, vb.y, hi, lo);
            Bh[row*SW + kp_b] = hi;
            Bl[row*SW + kp_b] = lo;
        }
        __syncthreads();
        mma_chunk(acc, Ah, Al, Bh, Bl, wm, wn, lid);
        __syncthreads();
    }

    float* o = lp + (size_t)blockIdx.x * COUT * COUT;
#pragma unroll
    for (int mt = 0; mt < 2; mt++) {
        int cc = (wm << 5) + (mt << 4) + (lid >> 2);
#pragma unroll
        for (int nt = 0; nt < 8; nt++) {
            int m = (wn << 6) + (nt << 3) + ((lid & 3) << 1);
            *(float2*)(o + (size_t)cc * COUT + m) =
                make_float2(acc[mt][nt][0], acc[mt][nt][1]);
            *(float2*)(o + (size_t)(cc + 8) * COUT + m) =
                make_float2(acc[mt][nt][2], acc[mt][nt][3]);
        }
    }
}

// ---------------------------------------------------------------------------
// Sum KSPL*DQ partials + row softmax over m. One block per (bn, c).
// ---------------------------------------------------------------------------
__global__ __launch_bounds__(128) void softmax_kernel(
    const float* __restrict__ lp, float* __restrict__ attn)
{
    const int row = blockIdx.x;
    const int bn  = row >> 7;
    const int c   = row & 127;
    const int m   = threadIdx.x;

    float s = 0.f;
#pragma unroll
    for (int ch = 0; ch < KSPL; ch++)
#pragma unroll
        for (int dd = 0; dd < DQ; dd++)
            s += lp[(((size_t)(ch*(B_*NH*DQ) + bn*DQ + dd))*COUT + c)*COUT + m];

    __shared__ float red[128];
    red[m] = s;
    __syncthreads();
    for (int off = 64; off > 0; off >>= 1) {
        if (m < off) red[m] = fmaxf(red[m], red[m + off]);
        __syncthreads();
    }
    float mx = red[0];
    __syncthreads();
    float e = expf(s - mx);
    red[m] = e;
    __syncthreads();
    for (int off = 64; off > 0; off >>= 1) {
        if (m < off) red[m] = red[m] + red[m + off];
        __syncthreads();
    }
    attn[row*COUT + m] = e / red[0];
}

// ---------------------------------------------------------------------------
// out[b,c,n*8+d,hw] = sum_m attn[bn,c,m] * v[b,m,n*8+d,hw]  (f32x2 scalar)
// ---------------------------------------------------------------------------
__global__ __launch_bounds__(256) void out_kernel(
    const float* __restrict__ attn, const float* __restrict__ v, float* __restrict__ out)
{
    const int tile = blockIdx.x;
    const int bn   = blockIdx.y;
    const int b    = bn >> 1;
    const int n    = bn & 1;
    const int d    = (tile << 6) >> 10;
    const int hw0  = (tile << 6) & 1023;
    const int tid  = threadIdx.x;
    const int px   = tid & 63;
    const int cg   = tid >> 6;
    const int c0   = cg << 5;
    const int hw   = hw0 + px;

    __shared__ float As2[64*132];
    const float* ab = attn + bn*COUT*COUT;
    const float* vb = v + ((size_t)b*COUT*LV + n*DV + d)*HW + hw;

    ull acc2[16];
#pragma unroll
    for (int j = 0; j < 16; j++) acc2[j] = 0ull;

    for (int mc = 0; mc < 2; mc++) {
        __syncthreads();
        for (int i = tid; i < 64*128; i += 256) {
            int ml = i & 63;
            int c  = i >> 6;
            As2[ml*132 + c] = ab[c*COUT + (mc << 6) + ml];
        }
        __syncthreads();
#pragma unroll 4
        for (int ml = 0; ml < 64; ml++) {
            float vv = vb[((size_t)((mc << 6) + ml))*(LV*HW)];
            ull vp = pack2(vv, vv);
            const ull* ap = (const ull*)&As2[ml*132 + c0];
#pragma unroll
            for (int jj = 0; jj < 16; jj++)
                ffma2(acc2[jj], ap[jj], vp);
        }
    }
    float* ob = out + (((size_t)b*COUT + c0)*(NH*DV) + n*DV + d)*HW + hw;
#pragma unroll
    for (int jj = 0; jj < 16; jj++) {
        float2 a = unpack2(acc2[jj]);
        ob[(size_t)(2*jj)    *(NH*DV*HW)] = a.x;
        ob[(size_t)(2*jj + 1)*(NH*DV*HW)] = a.y;
    }
}

// ---------------------------------------------------------------------------
extern "C" void kernel_launch(void* const* d_in, const int* in_sizes, int n_in,
                              void* d_out, int out_size)
{
    const float* input  = (const float*)d_in[0];
    const float* memory = (const float*)d_in[1];
    const float* wq = (const float*)d_in[2];
    const float* bq = (const float*)d_in[3];
    const float* wk = (const float*)d_in[4];
    const float* bk = (const float*)d_in[5];
    const float* wv = (const float*)d_in[6];
    const float* bv = (const float*)d_in[7];
    float* out = (float*)d_out;

    float *pq, *pk, *pv, *plp, *pattn;
    cudaGetSymbolAddress((void**)&pq,    g_q);
    cudaGetSymbolAddress((void**)&pk,    g_k);
    cudaGetSymbolAddress((void**)&pv,    g_v);
    cudaGetSymbolAddress((void**)&plp,   g_lp);
    cudaGetSymbolAddress((void**)&pattn, g_attn);

    conv_mma_kernel<9, L_> <<<dim3(8, L_, B_), 256>>>(input,  wq, bq, pq, 0.5f);
    conv_mma_kernel<9, L_> <<<dim3(8, L_, B_), 256>>>(memory, wk, bk, pk, 1.0f);
    conv_mma_kernel<27, LV><<<dim3(8, LV, B_), 256>>>(memory, wv, bv, pv, 1.0f);
    logit_mma_kernel       <<<KSPL*B_*NH*DQ, 256>>>(pq, pk, plp);
    softmax_kernel         <<<B_*NH*COUT, 128>>>(plp, pattn);
    out_kernel             <<<dim3(128, B_*NH), 256>>>(pattn, pv, out);
}

// round 11
// speedup vs baseline: 2.4330x; 1.0882x over previous
#include <cuda_runtime.h>
#include <cuda_fp16.h>
#include <cstdint>

#define B_   8
#define CIN  64
#define COUT 128
#define L_   18
#define LV   16
#define H_   32
#define W_   32
#define HW   1024
#define NH   2
#define DQ   9
#define DV   8
#define KSPL 2            // logit K split

// Scratch (static device globals; no runtime allocation allowed)
__device__ float g_q[B_*COUT*L_*HW];                // 75.5 MB
__device__ float g_k[B_*COUT*L_*HW];                // 75.5 MB
__device__ float g_v[B_*COUT*LV*HW];                // 67 MB
__device__ float g_lp[KSPL*B_*NH*DQ*COUT*COUT];     // 18.9 MB
__device__ float g_attn[B_*NH*COUT*COUT];           // 1 MB

typedef unsigned long long ull;

// ---------------------------------------------------------------------------
// fp16 split helpers
// ---------------------------------------------------------------------------
__device__ __forceinline__ uint32_t f2h2(float x0, float x1) {
    uint32_t r;
    asm("cvt.rn.f16x2.f32 %0, %1, %2;" : "=r"(r) : "f"(x1), "f"(x0));
    return r;   // lo half = x0, hi half = x1 (memory order)
}
__device__ __forceinline__ float2 h2f2(uint32_t u) {
    __half2 h = *(__half2*)&u;
    return __half22float2(h);
}
__device__ __forceinline__ void split2(float x0, float x1, uint32_t& hi, uint32_t& lo) {
    hi = f2h2(x0, x1);
    float2 hf = h2f2(hi);
    lo = f2h2(x0 - hf.x, x1 - hf.y);
}

// mma.sync m16n8k16 fp16 (baseline PTX, works on plain sm_103)
__device__ __forceinline__ void mma_f16(float* d, const uint32_t* a,
                                        uint32_t b0, uint32_t b1) {
    asm volatile(
        "mma.sync.aligned.m16n8k16.row.col.f32.f16.f16.f32 "
        "{%0,%1,%2,%3}, {%4,%5,%6,%7}, {%8,%9}, {%0,%1,%2,%3};"
        : "+f"(d[0]), "+f"(d[1]), "+f"(d[2]), "+f"(d[3])
        : "r"(a[0]), "r"(a[1]), "r"(a[2]), "r"(a[3]), "r"(b0), "r"(b1));
}

// f32x2 helpers (out_kernel)
__device__ __forceinline__ ull pack2(float x, float y) {
    ull r; asm("mov.b64 %0, {%1, %2};" : "=l"(r) : "f"(x), "f"(y)); return r;
}
__device__ __forceinline__ float2 unpack2(ull v) {
    float2 r; asm("mov.b64 {%0, %1}, %2;" : "=f"(r.x), "=f"(r.y) : "l"(v)); return r;
}
__device__ __forceinline__ void ffma2(ull& d, ull a, ull b) {
    asm("fma.rn.f32x2 %0, %1, %2, %0;" : "+l"(d) : "l"(a), "l"(b));
}

#define KC  32          // K elems per chunk
#define SW  20          // smem row stride in 32-bit words (16 data + 4 pad)

// ---------------------------------------------------------------------------
// Fragment-load + 3-segment MMA core shared by conv and logit kernels.
// acc += Ah*Bh + Al*Bh + Ah*Bl over the 32-k chunk in smem.
// ---------------------------------------------------------------------------
__device__ __forceinline__ void mma_chunk(
    float acc[2][8][4],
    const uint32_t* Ah, const uint32_t* Al,
    const uint32_t* Bh, const uint32_t* Bl,
    int wm, int wn, int lid)
{
    const int qr = lid >> 2;
    const int qc = lid & 3;
#pragma unroll
    for (int ks = 0; ks < 2; ks++) {
        const int base = ks << 3;
        uint32_t ah[2][4], al[2][4];
#pragma unroll
        for (int mt = 0; mt < 2; mt++) {
            int r0 = (wm << 5) + (mt << 4) + qr;
            int w0 = r0 * SW + base + qc;
            int w1 = (r0 + 8) * SW + base + qc;
            ah[mt][0] = Ah[w0];     ah[mt][1] = Ah[w1];
            ah[mt][2] = Ah[w0 + 4]; ah[mt][3] = Ah[w1 + 4];
            al[mt][0] = Al[w0];     al[mt][1] = Al[w1];
            al[mt][2] = Al[w0 + 4]; al[mt][3] = Al[w1 + 4];
        }
        uint32_t bf[8][2];
#pragma unroll
        for (int nt = 0; nt < 8; nt++) {
            int n = (wn << 6) + (nt << 3) + qr;
            int w = n * SW + base + qc;
            bf[nt][0] = Bh[w]; bf[nt][1] = Bh[w + 4];
        }
#pragma unroll
        for (int nt = 0; nt < 8; nt++) {
            mma_f16(acc[0][nt], ah[0], bf[nt][0], bf[nt][1]);
            mma_f16(acc[1][nt], ah[1], bf[nt][0], bf[nt][1]);
        }
#pragma unroll
        for (int nt = 0; nt < 8; nt++) {
            mma_f16(acc[0][nt], al[0], bf[nt][0], bf[nt][1]);
            mma_f16(acc[1][nt], al[1], bf[nt][0], bf[nt][1]);
        }
#pragma unroll
        for (int nt = 0; nt < 8; nt++) {
            int n = (wn << 6) + (nt << 3) + qr;
            int w = n * SW + base + qc;
            bf[nt][0] = Bl[w]; bf[nt][1] = Bl[w + 4];
        }
#pragma unroll
        for (int nt = 0; nt < 8; nt++) {
            mma_f16(acc[0][nt], ah[0], bf[nt][0], bf[nt][1]);
            mma_f16(acc[1][nt], ah[1], bf[nt][0], bf[nt][1]);
        }
    }
}

// ---------------------------------------------------------------------------
// Implicit-GEMM conv via mma.sync fp16x3 with register-prefetch pipeline.
// D[co=128, hw=128] = W[co, K] * P[hw, K], K = CIN*TAPS.
// grid (8 hw-tiles, LOUT, B_), block 256 (8 warps, each 32co x 64hw), 1 CTA/SM.
// ---------------------------------------------------------------------------
template<int TAPS, int LOUT>
__global__ __launch_bounds__(256, 1) void conv_mma_kernel(
    const float* __restrict__ in, const float* __restrict__ wgt,
    const float* __restrict__ bias, float* __restrict__ dst, float scale)
{
    constexpr int KSEG = CIN * TAPS;          // 576 or 1728
    constexpr int NCHUNK = KSEG / KC;         // 18 or 54
    __shared__ uint32_t Ah[128*SW], Al[128*SW], Bh[128*SW], Bl[128*SW];

    const int tid = threadIdx.x;
    const int wid = tid >> 5;
    const int lid = tid & 31;
    const int wm  = wid & 3;
    const int wn  = wid >> 2;
    const int l   = blockIdx.y;
    const int b   = blockIdx.z;
    const int hw0 = blockIdx.x << 7;

    const float* inb = in + (size_t)b*CIN*L_*HW + (size_t)l*HW;
    const int kp_b = tid & 15;       // k-pair index
    const int rw_b = tid >> 4;       // row base (stride 16)

    float acc[2][8][4];
#pragma unroll
    for (int i = 0; i < 2; i++)
#pragma unroll
        for (int j = 0; j < 8; j++)
#pragma unroll
            for (int r = 0; r < 4; r++) acc[i][j][r] = 0.f;

    float aw[16], bx[16];            // prefetch registers for one chunk

    auto loadA = [&](int tb) {
#pragma unroll
        for (int q = 0; q < 8; q++) {
            int row = rw_b + (q << 4);
            float2 v = *(const float2*)(wgt + (size_t)row * KSEG + tb + (kp_b << 1));
            aw[2*q] = v.x; aw[2*q + 1] = v.y;
        }
    };
    auto loadB = [&](int tb) {
        const int t0 = tb + (kp_b << 1);
#pragma unroll
        for (int e = 0; e < 2; e++) {
            int t   = t0 + e;
            int ci  = t / TAPS;
            int tap = t - ci * TAPS;
            int dl, dh, dw;
            if (TAPS == 27) { dl = tap / 9; int r = tap - dl * 9; dh = r / 3; dw = r - dh * 3; }
            else            { dl = 0; dh = tap / 3; dw = tap - dh * 3; }
            const float* base = inb + ((size_t)ci * L_ + dl) * HW;
#pragma unroll
            for (int q = 0; q < 8; q++) {
                int n = rw_b + (q << 4);
                int p = hw0 + n;
                int h = p >> 5;
                int w = p & 31;
                int hh = h + dh - 1, ww = w + dw - 1;
                float x = 0.f;
                if ((unsigned)hh < (unsigned)H_ && (unsigned)ww < (unsigned)W_)
                    x = base[hh * W_ + ww];
                bx[(q << 1) + e] = x;
            }
        }
    };

    loadA(0);
    loadB(0);

#pragma unroll 1
    for (int c = 0; c < NCHUNK; c++) {
        // Store prefetched chunk c (split hi/lo) into smem
#pragma unroll
        for (int q = 0; q < 8; q++) {
            int row = rw_b + (q << 4);
            uint32_t hi, lo;
            split2(aw[2*q], aw[2*q + 1], hi, lo);
            Ah[row*SW + kp_b] = hi;
            Al[row*SW + kp_b] = lo;
            split2(bx[2*q], bx[2*q + 1], hi, lo);
            Bh[row*SW + kp_b] = hi;
            Bl[row*SW + kp_b] = lo;
        }
        __syncthreads();
        // Prefetch chunk c+1 while the MMAs below fill the tensor pipe
        if (c + 1 < NCHUNK) {
            loadA((c + 1) * KC);
            loadB((c + 1) * KC);
        }
        mma_chunk(acc, Ah, Al, Bh, Bl, wm, wn, lid);
        __syncthreads();
    }

    // Epilogue
#pragma unroll
    for (int mt = 0; mt < 2; mt++) {
        int co = (wm << 5) + (mt << 4) + (lid >> 2);
        float bi0 = bias[co];
        float bi1 = bias[co + 8];
        float* d0 = dst + (((size_t)b * COUT + co)     * LOUT + l) * HW + hw0;
        float* d1 = dst + (((size_t)b * COUT + co + 8) * LOUT + l) * HW + hw0;
#pragma unroll
        for (int nt = 0; nt < 8; nt++) {
            int colp = (wn << 6) + (nt << 3) + ((lid & 3) << 1);
            *(float2*)(d0 + colp) = make_float2((acc[mt][nt][0] + bi0) * scale,
                                                (acc[mt][nt][1] + bi0) * scale);
            *(float2*)(d1 + colp) = make_float2((acc[mt][nt][2] + bi1) * scale,
                                                (acc[mt][nt][3] + bi1) * scale);
        }
    }
}

// ---------------------------------------------------------------------------
// Logit partial per (ck, b, n, d): D[c=128, m=128] = sum over 512 pixels.
// grid KSPL*144, block 256, register-prefetch pipeline.
// ---------------------------------------------------------------------------
__global__ __launch_bounds__(256, 1) void logit_mma_kernel(
    const float* __restrict__ q, const float* __restrict__ k, float* __restrict__ lp)
{
    constexpr int NCHUNK = HW / (KC * KSPL);  // 16
    __shared__ uint32_t Ah[128*SW], Al[128*SW], Bh[128*SW], Bl[128*SW];

    const int tid = threadIdx.x;
    const int wid = tid >> 5;
    const int lid = tid & 31;
    const int wm  = wid & 3;
    const int wn  = wid >> 2;
    const int ck  = blockIdx.x / (B_*NH*DQ);
    const int bnd = blockIdx.x % (B_*NH*DQ);
    const int d   = bnd % DQ;
    const int bn  = bnd / DQ;
    const int n_  = bn & 1;
    const int b   = bn >> 1;
    const int ldep = n_ * DQ + d;

    const float* qb = q + ((size_t)b * COUT * L_ + ldep) * HW;
    const float* kb = k + ((size_t)b * COUT * L_ + ldep) * HW;

    float acc[2][8][4];
#pragma unroll
    for (int i = 0; i < 2; i++)
#pragma unroll
        for (int j = 0; j < 8; j++)
#pragma unroll
            for (int r = 0; r < 4; r++) acc[i][j][r] = 0.f;

    const int kp_b = tid & 15;
    const int rw_b = tid >> 4;
    const int base0 = ck * (HW/KSPL);

    float aw[16], bx[16];
    auto loadQK = [&](int tb) {
#pragma unroll
        for (int qq = 0; qq < 8; qq++) {
            int row = rw_b + (qq << 4);
            float2 va = *(const float2*)(qb + (size_t)row * (L_*HW) + tb + (kp_b << 1));
            aw[2*qq] = va.x; aw[2*qq + 1] = va.y;
            float2 vb = *(const float2*)(kb + (size_t)row * (L_*HW) + tb + (kp_b << 1));
            bx[2*qq] = vb.x; bx[2*qq + 1] = vb.y;
        }
    };

    loadQK(base0);

#pragma unroll 1
    for (int c = 0; c < NCHUNK; c++) {
#pragma unroll
        for (int qq = 0; qq < 8; qq++) {
            int row = rw_b + (qq << 4);
            uint32_t hi, lo;
            split2(aw[2*qq], aw[2*qq + 1], hi, lo);
            Ah[row*SW + kp_b] = hi;
            Al[row*SW + kp_b] = lo;
            split2(bx[2*qq], bx[2*qq + 1], hi, lo);
            Bh[row*SW + kp_b] = hi;
            Bl[row*SW + kp_b] = lo;
        }
        __syncthreads();
        if (c + 1 < NCHUNK) loadQK(base0 + (c + 1) * KC);
        mma_chunk(acc, Ah, Al, Bh, Bl, wm, wn, lid);
        __syncthreads();
    }

    float* o = lp + (size_t)blockIdx.x * COUT * COUT;
#pragma unroll
    for (int mt = 0; mt < 2; mt++) {
        int cc = (wm << 5) + (mt << 4) + (lid >> 2);
#pragma unroll
        for (int nt = 0; nt < 8; nt++) {
            int m = (wn << 6) + (nt << 3) + ((lid & 3) << 1);
            *(float2*)(o + (size_t)cc * COUT + m) =
                make_float2(acc[mt][nt][0], acc[mt][nt][1]);
            *(float2*)(o + (size_t)(cc + 8) * COUT + m) =
                make_float2(acc[mt][nt][2], acc[mt][nt][3]);
        }
    }
}

// ---------------------------------------------------------------------------
// Sum KSPL*DQ partials + row softmax over m. One block per (bn, c).
// ---------------------------------------------------------------------------
__global__ __launch_bounds__(128) void softmax_kernel(
    const float* __restrict__ lp, float* __restrict__ attn)
{
    const int row = blockIdx.x;
    const int bn  = row >> 7;
    const int c   = row & 127;
    const int m   = threadIdx.x;

    float s = 0.f;
#pragma unroll
    for (int ch = 0; ch < KSPL; ch++)
#pragma unroll
        for (int dd = 0; dd < DQ; dd++)
            s += lp[(((size_t)(ch*(B_*NH*DQ) + bn*DQ + dd))*COUT + c)*COUT + m];

    __shared__ float red[128];
    red[m] = s;
    __syncthreads();
    for (int off = 64; off > 0; off >>= 1) {
        if (m < off) red[m] = fmaxf(red[m], red[m + off]);
        __syncthreads();
    }
    float mx = red[0];
    __syncthreads();
    float e = expf(s - mx);
    red[m] = e;
    __syncthreads();
    for (int off = 64; off > 0; off >>= 1) {
        if (m < off) red[m] = red[m] + red[m + off];
        __syncthreads();
    }
    attn[row*COUT + m] = e / red[0];
}

// ---------------------------------------------------------------------------
// out[b,c,n*8+d,hw] = sum_m attn[bn,c,m] * v[b,m,n*8+d,hw]  (f32x2 scalar)
// ---------------------------------------------------------------------------
__global__ __launch_bounds__(256) void out_kernel(
    const float* __restrict__ attn, const float* __restrict__ v, float* __restrict__ out)
{
    const int tile = blockIdx.x;
    const int bn   = blockIdx.y;
    const int b    = bn >> 1;
    const int n    = bn & 1;
    const int d    = (tile << 6) >> 10;
    const int hw0  = (tile << 6) & 1023;
    const int tid  = threadIdx.x;
    const int px   = tid & 63;
    const int cg   = tid >> 6;
    const int c0   = cg << 5;
    const int hw   = hw0 + px;

    __shared__ float As2[64*132];
    const float* ab = attn + bn*COUT*COUT;
    const float* vb = v + ((size_t)b*COUT*LV + n*DV + d)*HW + hw;

    ull acc2[16];
#pragma unroll
    for (int j = 0; j < 16; j++) acc2[j] = 0ull;

    for (int mc = 0; mc < 2; mc++) {
        __syncthreads();
        for (int i = tid; i < 64*128; i += 256) {
            int ml = i & 63;
            int c  = i >> 6;
            As2[ml*132 + c] = ab[c*COUT + (mc << 6) + ml];
        }
        __syncthreads();
#pragma unroll 4
        for (int ml = 0; ml < 64; ml++) {
            float vv = vb[((size_t)((mc << 6) + ml))*(LV*HW)];
            ull vp = pack2(vv, vv);
            const ull* ap = (const ull*)&As2[ml*132 + c0];
#pragma unroll
            for (int jj = 0; jj < 16; jj++)
                ffma2(acc2[jj], ap[jj], vp);
        }
    }
    float* ob = out + (((size_t)b*COUT + c0)*(NH*DV) + n*DV + d)*HW + hw;
#pragma unroll
    for (int jj = 0; jj < 16; jj++) {
        float2 a = unpack2(acc2[jj]);
        ob[(size_t)(2*jj)    *(NH*DV*HW)] = a.x;
        ob[(size_t)(2*jj + 1)*(NH*DV*HW)] = a.y;
    }
}

// ---------------------------------------------------------------------------
extern "C" void kernel_launch(void* const* d_in, const int* in_sizes, int n_in,
                              void* d_out, int out_size)
{
    const float* input  = (const float*)d_in[0];
    const float* memory = (const float*)d_in[1];
    const float* wq = (const float*)d_in[2];
    const float* bq = (const float*)d_in[3];
    const float* wk = (const float*)d_in[4];
    const float* bk = (const float*)d_in[5];
    const float* wv = (const float*)d_in[6];
    const float* bv = (const float*)d_in[7];
    float* out = (float*)d_out;

    float *pq, *pk, *pv, *plp, *pattn;
    cudaGetSymbolAddress((void**)&pq,    g_q);
    cudaGetSymbolAddress((void**)&pk,    g_k);
    cudaGetSymbolAddress((void**)&pv,    g_v);
    cudaGetSymbolAddress((void**)&plp,   g_lp);
    cudaGetSymbolAddress((void**)&pattn, g_attn);

    conv_mma_kernel<9, L_> <<<dim3(8, L_, B_), 256>>>(input,  wq, bq, pq, 0.5f);
    conv_mma_kernel<9, L_> <<<dim3(8, L_, B_), 256>>>(memory, wk, bk, pk, 1.0f);
    conv_mma_kernel<27, LV><<<dim3(8, LV, B_), 256>>>(memory, wv, bv, pv, 1.0f);
    logit_mma_kernel       <<<KSPL*B_*NH*DQ, 256>>>(pq, pk, plp);
    softmax_kernel         <<<B_*NH*COUT, 128>>>(plp, pattn);
    out_kernel             <<<dim3(128, B_*NH), 256>>>(pattn, pv, out);
}

// round 12
// speedup vs baseline: 2.5153x; 1.0338x over previous
#include <cuda_runtime.h>
#include <cuda_fp16.h>
#include <cstdint>

#define B_   8
#define CIN  64
#define COUT 128
#define L_   18
#define LV   16
#define H_   32
#define W_   32
#define HW   1024
#define NH   2
#define DQ   9
#define DV   8
#define KSPL 2            // logit K split

// Scratch (static device globals; no runtime allocation allowed)
__device__ float g_q[B_*COUT*L_*HW];                // 75.5 MB
__device__ float g_k[B_*COUT*L_*HW];                // 75.5 MB
__device__ float g_v[B_*COUT*LV*HW];                // 67 MB
__device__ float g_lp[KSPL*B_*NH*DQ*COUT*COUT];     // 18.9 MB
__device__ float g_attn[B_*NH*COUT*COUT];           // 1 MB

typedef unsigned long long ull;

// ---------------------------------------------------------------------------
// fp16 split helpers
// ---------------------------------------------------------------------------
__device__ __forceinline__ uint32_t f2h2(float x0, float x1) {
    uint32_t r;
    asm("cvt.rn.f16x2.f32 %0, %1, %2;" : "=r"(r) : "f"(x1), "f"(x0));
    return r;   // lo half = x0, hi half = x1 (memory order)
}
__device__ __forceinline__ float2 h2f2(uint32_t u) {
    __half2 h = *(__half2*)&u;
    return __half22float2(h);
}
__device__ __forceinline__ void split2(float x0, float x1, uint32_t& hi, uint32_t& lo) {
    hi = f2h2(x0, x1);
    float2 hf = h2f2(hi);
    lo = f2h2(x0 - hf.x, x1 - hf.y);
}

// mma.sync m16n8k16 fp16 (baseline PTX, works on plain sm_103)
__device__ __forceinline__ void mma_f16(float* d, const uint32_t* a,
                                        uint32_t b0, uint32_t b1) {
    asm volatile(
        "mma.sync.aligned.m16n8k16.row.col.f32.f16.f16.f32 "
        "{%0,%1,%2,%3}, {%4,%5,%6,%7}, {%8,%9}, {%0,%1,%2,%3};"
        : "+f"(d[0]), "+f"(d[1]), "+f"(d[2]), "+f"(d[3])
        : "r"(a[0]), "r"(a[1]), "r"(a[2]), "r"(a[3]), "r"(b0), "r"(b1));
}

// f32x2 helpers (out_kernel)
__device__ __forceinline__ ull pack2(float x, float y) {
    ull r; asm("mov.b64 %0, {%1, %2};" : "=l"(r) : "f"(x), "f"(y)); return r;
}
__device__ __forceinline__ float2 unpack2(ull v) {
    float2 r; asm("mov.b64 {%0, %1}, %2;" : "=f"(r.x), "=f"(r.y) : "l"(v)); return r;
}
__device__ __forceinline__ void ffma2(ull& d, ull a, ull b) {
    asm("fma.rn.f32x2 %0, %1, %2, %0;" : "+l"(d) : "l"(a), "l"(b));
}

#define KC   32          // K elems per chunk
#define SW   20          // A smem row stride (u32 words = k-pairs + pad)
#define SWB  136         // B smem k-pair-row stride (u32 words = pixels + pad)

// ---------------------------------------------------------------------------
// MMA core, conv variant: A [co][kp] stride SW, B [kp][px] stride SWB.
// acc += Ah*Bh + Al*Bh + Ah*Bl over the 32-k chunk in smem.
// ---------------------------------------------------------------------------
__device__ __forceinline__ void mma_chunk_bk(
    float acc[2][8][4],
    const uint32_t* Ah, const uint32_t* Al,
    const uint32_t* Bh, const uint32_t* Bl,
    int wm, int wn, int lid)
{
    const int qr = lid >> 2;
    const int qc = lid & 3;
#pragma unroll
    for (int ks = 0; ks < 2; ks++) {
        const int base = ks << 3;
        uint32_t ah[2][4], al[2][4];
#pragma unroll
        for (int mt = 0; mt < 2; mt++) {
            int r0 = (wm << 5) + (mt << 4) + qr;
            int w0 = r0 * SW + base + qc;
            int w1 = (r0 + 8) * SW + base + qc;
            ah[mt][0] = Ah[w0];     ah[mt][1] = Ah[w1];
            ah[mt][2] = Ah[w0 + 4]; ah[mt][3] = Ah[w1 + 4];
            al[mt][0] = Al[w0];     al[mt][1] = Al[w1];
            al[mt][2] = Al[w0 + 4]; al[mt][3] = Al[w1 + 4];
        }
        uint32_t bf[8][2];
#pragma unroll
        for (int nt = 0; nt < 8; nt++) {
            int n = (wn << 6) + (nt << 3) + qr;
            bf[nt][0] = Bh[(base + qc) * SWB + n];
            bf[nt][1] = Bh[(base + qc + 4) * SWB + n];
        }
#pragma unroll
        for (int nt = 0; nt < 8; nt++) {
            mma_f16(acc[0][nt], ah[0], bf[nt][0], bf[nt][1]);
            mma_f16(acc[1][nt], ah[1], bf[nt][0], bf[nt][1]);
        }
#pragma unroll
        for (int nt = 0; nt < 8; nt++) {
            mma_f16(acc[0][nt], al[0], bf[nt][0], bf[nt][1]);
            mma_f16(acc[1][nt], al[1], bf[nt][0], bf[nt][1]);
        }
#pragma unroll
        for (int nt = 0; nt < 8; nt++) {
            int n = (wn << 6) + (nt << 3) + qr;
            bf[nt][0] = Bl[(base + qc) * SWB + n];
            bf[nt][1] = Bl[(base + qc + 4) * SWB + n];
        }
#pragma unroll
        for (int nt = 0; nt < 8; nt++) {
            mma_f16(acc[0][nt], ah[0], bf[nt][0], bf[nt][1]);
            mma_f16(acc[1][nt], ah[1], bf[nt][0], bf[nt][1]);
        }
    }
}

// Logit variant: both A and B in [row][kp] layout, stride SW.
__device__ __forceinline__ void mma_chunk(
    float acc[2][8][4],
    const uint32_t* Ah, const uint32_t* Al,
    const uint32_t* Bh, const uint32_t* Bl,
    int wm, int wn, int lid)
{
    const int qr = lid >> 2;
    const int qc = lid & 3;
#pragma unroll
    for (int ks = 0; ks < 2; ks++) {
        const int base = ks << 3;
        uint32_t ah[2][4], al[2][4];
#pragma unroll
        for (int mt = 0; mt < 2; mt++) {
            int r0 = (wm << 5) + (mt << 4) + qr;
            int w0 = r0 * SW + base + qc;
            int w1 = (r0 + 8) * SW + base + qc;
            ah[mt][0] = Ah[w0];     ah[mt][1] = Ah[w1];
            ah[mt][2] = Ah[w0 + 4]; ah[mt][3] = Ah[w1 + 4];
            al[mt][0] = Al[w0];     al[mt][1] = Al[w1];
            al[mt][2] = Al[w0 + 4]; al[mt][3] = Al[w1 + 4];
        }
        uint32_t bf[8][2];
#pragma unroll
        for (int nt = 0; nt < 8; nt++) {
            int n = (wn << 6) + (nt << 3) + qr;
            int w = n * SW + base + qc;
            bf[nt][0] = Bh[w]; bf[nt][1] = Bh[w + 4];
        }
#pragma unroll
        for (int nt = 0; nt < 8; nt++) {
            mma_f16(acc[0][nt], ah[0], bf[nt][0], bf[nt][1]);
            mma_f16(acc[1][nt], ah[1], bf[nt][0], bf[nt][1]);
        }
#pragma unroll
        for (int nt = 0; nt < 8; nt++) {
            mma_f16(acc[0][nt], al[0], bf[nt][0], bf[nt][1]);
            mma_f16(acc[1][nt], al[1], bf[nt][0], bf[nt][1]);
        }
#pragma unroll
        for (int nt = 0; nt < 8; nt++) {
            int n = (wn << 6) + (nt << 3) + qr;
            int w = n * SW + base + qc;
            bf[nt][0] = Bl[w]; bf[nt][1] = Bl[w + 4];
        }
#pragma unroll
        for (int nt = 0; nt < 8; nt++) {
            mma_f16(acc[0][nt], ah[0], bf[nt][0], bf[nt][1]);
            mma_f16(acc[1][nt], ah[1], bf[nt][0], bf[nt][1]);
        }
    }
}

// ---------------------------------------------------------------------------
// Implicit-GEMM conv via mma.sync fp16x3, register prefetch, coalesced im2col.
// D[co=128, hw=128] = W[co, K] * P[hw, K], K = CIN*TAPS.
// grid (8 hw-tiles, LOUT, B_), block 256 (8 warps, each 32co x 64hw), 1 CTA/SM.
// ---------------------------------------------------------------------------
template<int TAPS, int LOUT>
__global__ __launch_bounds__(256, 1) void conv_mma_kernel(
    const float* __restrict__ in, const float* __restrict__ wgt,
    const float* __restrict__ bias, float* __restrict__ dst, float scale)
{
    constexpr int KSEG = CIN * TAPS;          // 576 or 1728
    constexpr int NCHUNK = KSEG / KC;         // 18 or 54
    __shared__ uint32_t Ah[128*SW], Al[128*SW];        // A: [co][kp]
    __shared__ uint32_t Bh[16*SWB], Bl[16*SWB];        // B: [kp][px]

    const int tid = threadIdx.x;
    const int wid = tid >> 5;
    const int lid = tid & 31;
    const int wm  = wid & 3;
    const int wn  = wid >> 2;
    const int l   = blockIdx.y;
    const int b   = blockIdx.z;
    const int hw0 = blockIdx.x << 7;

    const float* inb = in + (size_t)b*CIN*L_*HW + (size_t)l*HW;

    // A-build mapping: lanes along k (coalesced in wgt)
    const int kp_a = tid & 15;
    const int rw_a = tid >> 4;
    // B-build mapping: lanes along pixels (coalesced in input)
    const int px   = tid & 127;
    const int kq   = tid >> 7;                // 0/1
    const int bh_  = (hw0 + px) >> 5;
    const int bw_  = px & 31;

    float acc[2][8][4];
#pragma unroll
    for (int i = 0; i < 2; i++)
#pragma unroll
        for (int j = 0; j < 8; j++)
#pragma unroll
            for (int r = 0; r < 4; r++) acc[i][j][r] = 0.f;

    float aw[16], bx[16];            // prefetch registers for one chunk

    auto loadA = [&](int tb) {
#pragma unroll
        for (int q = 0; q < 8; q++) {
            int row = rw_a + (q << 4);
            float2 v = *(const float2*)(wgt + (size_t)row * KSEG + tb + (kp_a << 1));
            aw[2*q] = v.x; aw[2*q + 1] = v.y;
        }
    };
    // Coalesced im2col: per iteration fixed (ci,tap), lanes sweep pixels.
    auto loadB = [&](int tb) {
#pragma unroll
        for (int it = 0; it < 8; it++) {
            int kp = (it << 1) + kq;
#pragma unroll
            for (int e = 0; e < 2; e++) {
                int t   = tb + (kp << 1) + e;
                int ci  = t / TAPS;
                int tap = t - ci * TAPS;
                int dl, dh, dw;
                if (TAPS == 27) { dl = tap / 9; int r = tap - dl * 9; dh = r / 3; dw = r - dh * 3; }
                else            { dl = 0; dh = tap / 3; dw = tap - dh * 3; }
                int hh = bh_ + dh - 1, ww = bw_ + dw - 1;
                float x = 0.f;
                if ((unsigned)hh < (unsigned)H_ && (unsigned)ww < (unsigned)W_)
                    x = inb[((size_t)ci * L_ + dl) * HW + hh * W_ + ww];
                bx[(it << 1) + e] = x;
            }
        }
    };

    loadA(0);
    loadB(0);

#pragma unroll 1
    for (int c = 0; c < NCHUNK; c++) {
        // Store prefetched chunk c (split hi/lo) into smem
#pragma unroll
        for (int q = 0; q < 8; q++) {
            int row = rw_a + (q << 4);
            uint32_t hi, lo;
            split2(aw[2*q], aw[2*q + 1], hi, lo);
            Ah[row*SW + kp_a] = hi;
            Al[row*SW + kp_a] = lo;
        }
#pragma unroll
        for (int it = 0; it < 8; it++) {
            int kp = (it << 1) + kq;
            uint32_t hi, lo;
            split2(bx[2*it], bx[2*it + 1], hi, lo);
            Bh[kp*SWB + px] = hi;
            Bl[kp*SWB + px] = lo;
        }
        __syncthreads();
        // Prefetch chunk c+1 while the MMAs below fill the tensor pipe
        if (c + 1 < NCHUNK) {
            loadA((c + 1) * KC);
            loadB((c + 1) * KC);
        }
        mma_chunk_bk(acc, Ah, Al, Bh, Bl, wm, wn, lid);
        __syncthreads();
    }

    // Epilogue
#pragma unroll
    for (int mt = 0; mt < 2; mt++) {
        int co = (wm << 5) + (mt << 4) + (lid >> 2);
        float bi0 = bias[co];
        float bi1 = bias[co + 8];
        float* d0 = dst + (((size_t)b * COUT + co)     * LOUT + l) * HW + hw0;
        float* d1 = dst + (((size_t)b * COUT + co + 8) * LOUT + l) * HW + hw0;
#pragma unroll
        for (int nt = 0; nt < 8; nt++) {
            int colp = (wn << 6) + (nt << 3) + ((lid & 3) << 1);
            *(float2*)(d0 + colp) = make_float2((acc[mt][nt][0] + bi0) * scale,
                                                (acc[mt][nt][1] + bi0) * scale);
            *(float2*)(d1 + colp) = make_float2((acc[mt][nt][2] + bi1) * scale,
                                                (acc[mt][nt][3] + bi1) * scale);
        }
    }
}

// ---------------------------------------------------------------------------
// Logit partial per (ck, b, n, d): D[c=128, m=128] = sum over 512 pixels.
// grid KSPL*144, block 256, register-prefetch pipeline. (Loads already
// coalesced; keeps [row][kp] layout.)
// ---------------------------------------------------------------------------
__global__ __launch_bounds__(256, 1) void logit_mma_kernel(
    const float* __restrict__ q, const float* __restrict__ k, float* __restrict__ lp)
{
    constexpr int NCHUNK = HW / (KC * KSPL);  // 16
    __shared__ uint32_t Ah[128*SW], Al[128*SW], Bh[128*SW], Bl[128*SW];

    const int tid = threadIdx.x;
    const int wid = tid >> 5;
    const int lid = tid & 31;
    const int wm  = wid & 3;
    const int wn  = wid >> 2;
    const int ck  = blockIdx.x / (B_*NH*DQ);
    const int bnd = blockIdx.x % (B_*NH*DQ);
    const int d   = bnd % DQ;
    const int bn  = bnd / DQ;
    const int n_  = bn & 1;
    const int b   = bn >> 1;
    const int ldep = n_ * DQ + d;

    const float* qb = q + ((size_t)b * COUT * L_ + ldep) * HW;
    const float* kb = k + ((size_t)b * COUT * L_ + ldep) * HW;

    float acc[2][8][4];
#pragma unroll
    for (int i = 0; i < 2; i++)
#pragma unroll
        for (int j = 0; j < 8; j++)
#pragma unroll
            for (int r = 0; r < 4; r++) acc[i][j][r] = 0.f;

    const int kp_b = tid & 15;
    const int rw_b = tid >> 4;
    const int base0 = ck * (HW/KSPL);

    float aw[16], bx[16];
    auto loadQK = [&](int tb) {
#pragma unroll
        for (int qq = 0; qq < 8; qq++) {
            int row = rw_b + (qq << 4);
            float2 va = *(const float2*)(qb + (size_t)row * (L_*HW) + tb + (kp_b << 1));
            aw[2*qq] = va.x; aw[2*qq + 1] = va.y;
            float2 vb = *(const float2*)(kb + (size_t)row * (L_*HW) + tb + (kp_b << 1));
            bx[2*qq] = vb.x; bx[2*qq + 1] = vb.y;
        }
    };

    loadQK(base0);

#pragma unroll 1
    for (int c = 0; c < NCHUNK; c++) {
#pragma unroll
        for (int qq = 0; qq < 8; qq++) {
            int row = rw_b + (qq << 4);
            uint32_t hi, lo;
            split2(aw[2*qq], aw[2*qq + 1], hi, lo);
            Ah[row*SW + kp_b] = hi;
            Al[row*SW + kp_b] = lo;
            split2(bx[2*qq], bx[2*qq + 1], hi, lo);
            Bh[row*SW + kp_b] = hi;
            Bl[row*SW + kp_b] = lo;
        }
        __syncthreads();
        if (c + 1 < NCHUNK) loadQK(base0 + (c + 1) * KC);
        mma_chunk(acc, Ah, Al, Bh, Bl, wm, wn, lid);
        __syncthreads();
    }

    float* o = lp + (size_t)blockIdx.x * COUT * COUT;
#pragma unroll
    for (int mt = 0; mt < 2; mt++) {
        int cc = (wm << 5) + (mt << 4) + (lid >> 2);
#pragma unroll
        for (int nt = 0; nt < 8; nt++) {
            int m = (wn << 6) + (nt << 3) + ((lid & 3) << 1);
            *(float2*)(o + (size_t)cc * COUT + m) =
                make_float2(acc[mt][nt][0], acc[mt][nt][1]);
            *(float2*)(o + (size_t)(cc + 8) * COUT + m) =
                make_float2(acc[mt][nt][2], acc[mt][nt][3]);
        }
    }
}

// ---------------------------------------------------------------------------
// Sum KSPL*DQ partials + row softmax over m. One block per (bn, c).
// ---------------------------------------------------------------------------
__global__ __launch_bounds__(128) void softmax_kernel(
    const float* __restrict__ lp, float* __restrict__ attn)
{
    const int row = blockIdx.x;
    const int bn  = row >> 7;
    const int c   = row & 127;
    const int m   = threadIdx.x;

    float s = 0.f;
#pragma unroll
    for (int ch = 0; ch < KSPL; ch++)
#pragma unroll
        for (int dd = 0; dd < DQ; dd++)
            s += lp[(((size_t)(ch*(B_*NH*DQ) + bn*DQ + dd))*COUT + c)*COUT + m];

    __shared__ float red[128];
    red[m] = s;
    __syncthreads();
    for (int off = 64; off > 0; off >>= 1) {
        if (m < off) red[m] = fmaxf(red[m], red[m + off]);
        __syncthreads();
    }
    float mx = red[0];
    __syncthreads();
    float e = expf(s - mx);
    red[m] = e;
    __syncthreads();
    for (int off = 64; off > 0; off >>= 1) {
        if (m < off) red[m] = red[m] + red[m + off];
        __syncthreads();
    }
    attn[row*COUT + m] = e / red[0];
}

// ---------------------------------------------------------------------------
// out[b,c,n*8+d,hw] = sum_m attn[bn,c,m] * v[b,m,n*8+d,hw]  (f32x2 scalar)
// ---------------------------------------------------------------------------
__global__ __launch_bounds__(256) void out_kernel(
    const float* __restrict__ attn, const float* __restrict__ v, float* __restrict__ out)
{
    const int tile = blockIdx.x;
    const int bn   = blockIdx.y;
    const int b    = bn >> 1;
    const int n    = bn & 1;
    const int d    = (tile << 6) >> 10;
    const int hw0  = (tile << 6) & 1023;
    const int tid  = threadIdx.x;
    const int px   = tid & 63;
    const int cg   = tid >> 6;
    const int c0   = cg << 5;
    const int hw   = hw0 + px;

    __shared__ float As2[64*132];
    const float* ab = attn + bn*COUT*COUT;
    const float* vb = v + ((size_t)b*COUT*LV + n*DV + d)*HW + hw;

    ull acc2[16];
#pragma unroll
    for (int j = 0; j < 16; j++) acc2[j] = 0ull;

    for (int mc = 0; mc < 2; mc++) {
        __syncthreads();
        for (int i = tid; i < 64*128; i += 256) {
            int ml = i & 63;
            int c  = i >> 6;
            As2[ml*132 + c] = ab[c*COUT + (mc << 6) + ml];
        }
        __syncthreads();
#pragma unroll 4
        for (int ml = 0; ml < 64; ml++) {
            float vv = vb[((size_t)((mc << 6) + ml))*(LV*HW)];
            ull vp = pack2(vv, vv);
            const ull* ap = (const ull*)&As2[ml*132 + c0];
#pragma unroll
            for (int jj = 0; jj < 16; jj++)
                ffma2(acc2[jj], ap[jj], vp);
        }
    }
    float* ob = out + (((size_t)b*COUT + c0)*(NH*DV) + n*DV + d)*HW + hw;
#pragma unroll
    for (int jj = 0; jj < 16; jj++) {
        float2 a = unpack2(acc2[jj]);
        ob[(size_t)(2*jj)    *(NH*DV*HW)] = a.x;
        ob[(size_t)(2*jj + 1)*(NH*DV*HW)] = a.y;
    }
}

// ---------------------------------------------------------------------------
extern "C" void kernel_launch(void* const* d_in, const int* in_sizes, int n_in,
                              void* d_out, int out_size)
{
    const float* input  = (const float*)d_in[0];
    const float* memory = (const float*)d_in[1];
    const float* wq = (const float*)d_in[2];
    const float* bq = (const float*)d_in[3];
    const float* wk = (const float*)d_in[4];
    const float* bk = (const float*)d_in[5];
    const float* wv = (const float*)d_in[6];
    const float* bv = (const float*)d_in[7];
    float* out = (float*)d_out;

    float *pq, *pk, *pv, *plp, *pattn;
    cudaGetSymbolAddress((void**)&pq,    g_q);
    cudaGetSymbolAddress((void**)&pk,    g_k);
    cudaGetSymbolAddress((void**)&pv,    g_v);
    cudaGetSymbolAddress((void**)&plp,   g_lp);
    cudaGetSymbolAddress((void**)&pattn, g_attn);

    conv_mma_kernel<9, L_> <<<dim3(8, L_, B_), 256>>>(input,  wq, bq, pq, 0.5f);
    conv_mma_kernel<9, L_> <<<dim3(8, L_, B_), 256>>>(memory, wk, bk, pk, 1.0f);
    conv_mma_kernel<27, LV><<<dim3(8, LV, B_), 256>>>(memory, wv, bv, pv, 1.0f);
    logit_mma_kernel       <<<KSPL*B_*NH*DQ, 256>>>(pq, pk, plp);
    softmax_kernel         <<<B_*NH*COUT, 128>>>(plp, pattn);
    out_kernel             <<<dim3(128, B_*NH), 256>>>(pattn, pv, out);
}